// round 1
// baseline (speedup 1.0000x reference)
#include <cuda_runtime.h>
#include <math.h>

// ---- problem constants ----
#define BB 16
#define CC 256
#define HH 96
#define WW 96
#define HWP (HH*WW)                 // 9216
#define NELEM (BB*CC*HWP)           // 37748736
#define S0 24
#define S1 48
#define S2 72

// ---- scratch (device globals: allocation-free rule) ----
__device__ float g_y[NELEM];
__device__ float g_z[NELEM];
__device__ float g_d0[BB*CC*S0*S0];
__device__ float g_d1[BB*CC*S1*S1];
__device__ float g_d2[BB*CC*S2*S2];
__device__ float g_dogk[CC*3];      // per-channel DoG difference kernel: center, edge, corner

// ---------------------------------------------------------------------------
// K0: per-channel DoG difference-kernel coefficients
// sig = 2*sigmoid(raw); k = exp(-r2/(2 sig^2)) / norm ; diff = k1 - k2
// ---------------------------------------------------------------------------
__global__ void k_params(const float* __restrict__ s1r, const float* __restrict__ s2r) {
    int c = threadIdx.x;
    float s1 = 2.f / (1.f + expf(-s1r[c]));
    float s2 = 2.f / (1.f + expf(-s2r[c]));
    float e1 = expf(-1.f / (2.f * s1 * s1)); float q1 = expf(-1.f / (s1 * s1));
    float e2 = expf(-1.f / (2.f * s2 * s2)); float q2 = expf(-1.f / (s2 * s2));
    float n1 = 1.f + 4.f * e1 + 4.f * q1;
    float n2 = 1.f + 4.f * e2 + 4.f * q2;
    g_dogk[c*3+0] = 1.f/n1 - 1.f/n2;
    g_dogk[c*3+1] = e1/n1 - e2/n2;
    g_dogk[c*3+2] = q1/n1 - q2/n2;
}

// ---------------------------------------------------------------------------
// K1: y = dec + skip (vectorized)
// ---------------------------------------------------------------------------
__global__ void k_add(const float4* __restrict__ a, const float4* __restrict__ b,
                      float4* __restrict__ o, int n) {
    int i = blockIdx.x * blockDim.x + threadIdx.x;
    if (i < n) {
        float4 x = a[i], y = b[i];
        o[i] = make_float4(x.x + y.x, x.y + y.y, x.z + y.z, x.w + y.w);
    }
}

// ---------------------------------------------------------------------------
// K2: bilinear downsample 96x96 -> SxS (half-pixel, clamped == jax renormalized)
// ---------------------------------------------------------------------------
__global__ void k_down(const float* __restrict__ y, float* __restrict__ out,
                       int S, float sf /* = 96/S */, int total) {
    int idx = blockIdx.x * blockDim.x + threadIdx.x;
    if (idx >= total) return;
    int ox = idx % S;
    int oy = (idx / S) % S;
    int bc = idx / (S * S);
    const float* p = y + (size_t)bc * HWP;

    float fy = fmaxf((oy + 0.5f) * sf - 0.5f, 0.f);
    float fx = fmaxf((ox + 0.5f) * sf - 0.5f, 0.f);
    int y0 = (int)fy, x0 = (int)fx;
    float wy = fy - y0, wx = fx - x0;
    int y1 = min(y0 + 1, HH - 1), x1 = min(x0 + 1, WW - 1);
    float v00 = p[y0*WW + x0], v01 = p[y0*WW + x1];
    float v10 = p[y1*WW + x0], v11 = p[y1*WW + x1];
    out[idx] = (v00*(1.f-wx) + v01*wx)*(1.f-wy) + (v10*(1.f-wx) + v11*wx)*wy;
}

// ---------------------------------------------------------------------------
// upsample gather helper (clamped bilinear; fy/fx pre-clamped >= 0)
// ---------------------------------------------------------------------------
__device__ __forceinline__ float up_bilin(const float* __restrict__ p, int S,
                                          float fy, float fx) {
    int y0 = (int)fy, x0 = (int)fx;
    float wy = fy - y0, wx = fx - x0;
    int y1 = min(y0 + 1, S - 1), x1 = min(x0 + 1, S - 1);
    float v00 = p[y0*S + x0], v01 = p[y0*S + x1];
    float v10 = p[y1*S + x0], v11 = p[y1*S + x1];
    return (v00*(1.f-wx) + v01*wx)*(1.f-wy) + (v10*(1.f-wx) + v11*wx)*wy;
}

// ---------------------------------------------------------------------------
// K3: fused FEA edges + DoG + combine:
//   z = 3*y + w_fea * w_edge + dwconv(y, k1-k2)
// ---------------------------------------------------------------------------
__global__ void k_fuse(const float* __restrict__ wfea) {
    int idx = blockIdx.x * blockDim.x + threadIdx.x;
    if (idx >= NELEM) return;
    int w = idx % WW;
    int h = (idx / WW) % HH;
    int bc = idx / HWP;
    int c = bc % CC;

    const float* yp = g_y + (size_t)bc * HWP;
    float yc = yp[h*WW + w];

    // DoG via 3x3 difference kernel, zero padding (SAME)
    float dC = g_dogk[c*3+0], dE = g_dogk[c*3+1], dX = g_dogk[c*3+2];
    bool hu = h > 0, hd = h < HH-1, wl = w > 0, wr = w < WW-1;
    float nU = hu ? yp[(h-1)*WW + w] : 0.f;
    float nD = hd ? yp[(h+1)*WW + w] : 0.f;
    float nL = wl ? yp[h*WW + (w-1)] : 0.f;
    float nR = wr ? yp[h*WW + (w+1)] : 0.f;
    float c00 = (hu && wl) ? yp[(h-1)*WW + (w-1)] : 0.f;
    float c01 = (hu && wr) ? yp[(h-1)*WW + (w+1)] : 0.f;
    float c10 = (hd && wl) ? yp[(h+1)*WW + (w-1)] : 0.f;
    float c11 = (hd && wr) ? yp[(h+1)*WW + (w+1)] : 0.f;
    float dog = dC*yc + dE*(nU+nD+nL+nR) + dX*(c00+c01+c10+c11);

    // Multi-scale edge maps: |y - up(down(y))|
    const float* p0 = g_d0 + (size_t)bc * (S0*S0);
    const float* p1 = g_d1 + (size_t)bc * (S1*S1);
    const float* p2 = g_d2 + (size_t)bc * (S2*S2);
    float fy0 = fmaxf((h + 0.5f) * (S0/96.f) - 0.5f, 0.f);
    float fx0 = fmaxf((w + 0.5f) * (S0/96.f) - 0.5f, 0.f);
    float fy1 = fmaxf((h + 0.5f) * (S1/96.f) - 0.5f, 0.f);
    float fx1 = fmaxf((w + 0.5f) * (S1/96.f) - 0.5f, 0.f);
    float fy2 = fmaxf((h + 0.5f) * (S2/96.f) - 0.5f, 0.f);
    float fx2 = fmaxf((w + 0.5f) * (S2/96.f) - 0.5f, 0.f);
    float e0 = fabsf(yc - up_bilin(p0, S0, fy0, fx0));
    float e1 = fabsf(yc - up_bilin(p1, S1, fy1, fx1));
    float e2 = fabsf(yc - up_bilin(p2, S2, fy2, fx2));
    float wedge = (fabsf(e0-e1) + fabsf(e0-e2) + fabsf(e1-e2)) * (1.f/3.f);

    g_z[idx] = 3.f*yc + wfea[c]*wedge + dog;
}

// ---------------------------------------------------------------------------
// K4: 1x1 mixer as GEMM + skip epilogue.
//   out[b,co,p] = sum_ci W[co,ci] * z[b,ci,p] + skip[b,co,p]
// 128x128 tile, BK=8, 256 threads, 8x8 microtile per thread, fp32.
// ---------------------------------------------------------------------------
#define BM 128
#define BN 128
#define BK 8

__global__ void __launch_bounds__(256) k_gemm(const float* __restrict__ Wm,
                                              const float* __restrict__ skip,
                                              float* __restrict__ out) {
    __shared__ float As[BK][BM];
    __shared__ float Bs[BK][BN];
    int b   = blockIdx.z;
    int co0 = blockIdx.y * BM;
    int p0  = blockIdx.x * BN;
    const float* Z = g_z + (size_t)b * CC * HWP;

    int t  = threadIdx.x;
    int tm = t >> 4, tn = t & 15;

    int arow = t >> 1, aseg = t & 1;    // A loader: 128 rows x 2 float4 segs
    int brow = t >> 5, bcol = t & 31;   // B loader: 8 rows x 32 float4 cols

    float acc[8][8];
#pragma unroll
    for (int i = 0; i < 8; i++)
#pragma unroll
        for (int j = 0; j < 8; j++) acc[i][j] = 0.f;

    for (int k0 = 0; k0 < CC; k0 += BK) {
        float4 av = *(const float4*)&Wm[(co0 + arow) * CC + k0 + aseg * 4];
        As[aseg*4+0][arow] = av.x;
        As[aseg*4+1][arow] = av.y;
        As[aseg*4+2][arow] = av.z;
        As[aseg*4+3][arow] = av.w;
        float4 bv = *(const float4*)&Z[(size_t)(k0 + brow) * HWP + p0 + bcol * 4];
        *(float4*)&Bs[brow][bcol * 4] = bv;
        __syncthreads();
#pragma unroll
        for (int kk = 0; kk < BK; ++kk) {
            float a[8], bb[8];
#pragma unroll
            for (int i = 0; i < 8; i++) a[i]  = As[kk][tm*8 + i];
#pragma unroll
            for (int j = 0; j < 8; j++) bb[j] = Bs[kk][tn*8 + j];
#pragma unroll
            for (int i = 0; i < 8; i++)
#pragma unroll
                for (int j = 0; j < 8; j++)
                    acc[i][j] += a[i] * bb[j];
        }
        __syncthreads();
    }

    size_t base = (size_t)b * CC * HWP;
#pragma unroll
    for (int i = 0; i < 8; i++) {
        int co = co0 + tm*8 + i;
        size_t row = base + (size_t)co * HWP + p0 + tn*8;
#pragma unroll
        for (int j = 0; j < 8; j += 4) {
            float4 s = *(const float4*)&skip[row + j];
            float4 o = make_float4(acc[i][j]   + s.x, acc[i][j+1] + s.y,
                                   acc[i][j+2] + s.z, acc[i][j+3] + s.w);
            *(float4*)&out[row + j] = o;
        }
    }
}

// ---------------------------------------------------------------------------
extern "C" void kernel_launch(void* const* d_in, const int* in_sizes, int n_in,
                              void* d_out, int out_size) {
    const float* skip   = (const float*)d_in[0];
    const float* dec    = (const float*)d_in[1];
    const float* w_fea  = (const float*)d_in[2];
    const float* sigma1 = (const float*)d_in[3];
    const float* sigma2 = (const float*)d_in[4];
    const float* mixerw = (const float*)d_in[5];
    float* out = (float*)d_out;

    float* yg; cudaGetSymbolAddress((void**)&yg, g_y);
    float* d0; cudaGetSymbolAddress((void**)&d0, g_d0);
    float* d1; cudaGetSymbolAddress((void**)&d1, g_d1);
    float* d2; cudaGetSymbolAddress((void**)&d2, g_d2);

    // K0: DoG coefficients
    k_params<<<1, CC>>>(sigma1, sigma2);

    // K1: y = dec + skip
    int n4 = NELEM / 4;
    k_add<<<(n4 + 255) / 256, 256>>>((const float4*)dec, (const float4*)skip,
                                     (float4*)yg, n4);

    // K2: three downsamples
    {
        int t0 = BB*CC*S0*S0; k_down<<<(t0 + 255)/256, 256>>>(yg, d0, S0, 96.f/S0, t0);
        int t1 = BB*CC*S1*S1; k_down<<<(t1 + 255)/256, 256>>>(yg, d1, S1, 96.f/S1, t1);
        int t2 = BB*CC*S2*S2; k_down<<<(t2 + 255)/256, 256>>>(yg, d2, S2, 96.f/S2, t2);
    }

    // K3: fused edges + DoG + combine -> z
    k_fuse<<<NELEM / 256, 256>>>(w_fea);

    // K4: 1x1 mixer GEMM + skip
    dim3 grid(HWP / BN, CC / BM, BB);
    k_gemm<<<grid, 256>>>(mixerw, skip, out);
}

// round 3
// speedup vs baseline: 1.4726x; 1.4726x over previous
#include <cuda_runtime.h>
#include <cuda_bf16.h>
#include <math.h>
#include <stdint.h>

// ---- problem constants ----
#define BB 16
#define CC 256
#define HH 96
#define WW 96
#define HWP (HH*WW)                 // 9216
#define NELEM (BB*CC*HWP)           // 37748736
#define S0 24
#define S1 48
#define S2 72

// ---- scratch (device globals: allocation-free rule) ----
__device__ float g_y[NELEM];
__device__ __nv_bfloat16 g_zh[NELEM];
__device__ __nv_bfloat16 g_zl[NELEM];
__device__ __nv_bfloat16 g_wh[CC*CC];
__device__ __nv_bfloat16 g_wl[CC*CC];
__device__ float g_d0[BB*CC*S0*S0];
__device__ float g_d1[BB*CC*S1*S1];
__device__ float g_d2[BB*CC*S2*S2];
__device__ float g_dogk[CC*3];

// ===========================================================================
// PTX helpers (family-portable: ldmatrix / mma.sync / cp.async only)
// ===========================================================================
__device__ __forceinline__ uint32_t smem_u32(const void* p) {
    uint32_t a;
    asm("{ .reg .u64 t; cvta.to.shared.u64 t, %1; cvt.u32.u64 %0, t; }"
        : "=r"(a) : "l"(p));
    return a;
}
#define CP16(dst, src) asm volatile( \
    "cp.async.cg.shared.global [%0], [%1], 16;" :: "r"(dst), "l"(src) : "memory")
#define CP_COMMIT() asm volatile("cp.async.commit_group;" ::: "memory")
#define CP_WAIT1() asm volatile("cp.async.wait_group 1;" ::: "memory")
#define CP_WAIT0() asm volatile("cp.async.wait_group 0;" ::: "memory")

__device__ __forceinline__ void ldsm_x4(uint32_t* r, uint32_t addr) {
    asm volatile("ldmatrix.sync.aligned.m8n8.x4.shared.b16 {%0,%1,%2,%3}, [%4];"
                 : "=r"(r[0]), "=r"(r[1]), "=r"(r[2]), "=r"(r[3]) : "r"(addr));
}
__device__ __forceinline__ void ldsm_x4_t(uint32_t* r, uint32_t addr) {
    asm volatile("ldmatrix.sync.aligned.m8n8.x4.trans.shared.b16 {%0,%1,%2,%3}, [%4];"
                 : "=r"(r[0]), "=r"(r[1]), "=r"(r[2]), "=r"(r[3]) : "r"(addr));
}
__device__ __forceinline__ void mma_bf16(float* c, const uint32_t* a, const uint32_t* b) {
    asm volatile(
        "mma.sync.aligned.m16n8k16.row.col.f32.bf16.bf16.f32 "
        "{%0,%1,%2,%3}, {%4,%5,%6,%7}, {%8,%9}, {%0,%1,%2,%3};"
        : "+f"(c[0]), "+f"(c[1]), "+f"(c[2]), "+f"(c[3])
        : "r"(a[0]), "r"(a[1]), "r"(a[2]), "r"(a[3]), "r"(b[0]), "r"(b[1]));
}

// ===========================================================================
// K0: per-channel DoG difference-kernel coefficients
// ===========================================================================
__global__ void k_params(const float* __restrict__ s1r, const float* __restrict__ s2r) {
    int c = threadIdx.x;
    float s1 = 2.f / (1.f + expf(-s1r[c]));
    float s2 = 2.f / (1.f + expf(-s2r[c]));
    float e1 = expf(-1.f / (2.f * s1 * s1)); float q1 = expf(-1.f / (s1 * s1));
    float e2 = expf(-1.f / (2.f * s2 * s2)); float q2 = expf(-1.f / (s2 * s2));
    float n1 = 1.f + 4.f * e1 + 4.f * q1;
    float n2 = 1.f + 4.f * e2 + 4.f * q2;
    g_dogk[c*3+0] = 1.f/n1 - 1.f/n2;
    g_dogk[c*3+1] = e1/n1 - e2/n2;
    g_dogk[c*3+2] = q1/n1 - q2/n2;
}

// K0b: split mixer weight into bf16 hi/lo
__global__ void k_wsplit(const float* __restrict__ w) {
    int i = blockIdx.x * 256 + threadIdx.x;
    float v = w[i];
    __nv_bfloat16 h = __float2bfloat16(v);
    g_wh[i] = h;
    g_wl[i] = __float2bfloat16(v - __bfloat162float(h));
}

// ===========================================================================
// K1: y = dec + skip
// ===========================================================================
__global__ void k_add(const float4* __restrict__ a, const float4* __restrict__ b,
                      float4* __restrict__ o, int n) {
    int i = blockIdx.x * blockDim.x + threadIdx.x;
    if (i < n) {
        float4 x = a[i], y = b[i];
        o[i] = make_float4(x.x + y.x, x.y + y.y, x.z + y.z, x.w + y.w);
    }
}

// ===========================================================================
// K2: bilinear downsample 96x96 -> SxS
// ===========================================================================
__global__ void k_down(const float* __restrict__ y, float* __restrict__ out,
                       int S, float sf, int total) {
    int idx = blockIdx.x * blockDim.x + threadIdx.x;
    if (idx >= total) return;
    int ox = idx % S;
    int oy = (idx / S) % S;
    int bc = idx / (S * S);
    const float* p = y + (size_t)bc * HWP;

    float fy = fmaxf((oy + 0.5f) * sf - 0.5f, 0.f);
    float fx = fmaxf((ox + 0.5f) * sf - 0.5f, 0.f);
    int y0 = (int)fy, x0 = (int)fx;
    float wy = fy - y0, wx = fx - x0;
    int y1 = min(y0 + 1, HH - 1), x1 = min(x0 + 1, WW - 1);
    float v00 = p[y0*WW + x0], v01 = p[y0*WW + x1];
    float v10 = p[y1*WW + x0], v11 = p[y1*WW + x1];
    out[idx] = (v00*(1.f-wx) + v01*wx)*(1.f-wy) + (v10*(1.f-wx) + v11*wx)*wy;
}

__device__ __forceinline__ float up_bilin(const float* __restrict__ p, int S,
                                          float fy, float fx) {
    int y0 = (int)fy, x0 = (int)fx;
    float wy = fy - y0, wx = fx - x0;
    int y1 = min(y0 + 1, S - 1), x1 = min(x0 + 1, S - 1);
    float v00 = p[y0*S + x0], v01 = p[y0*S + x1];
    float v10 = p[y1*S + x0], v11 = p[y1*S + x1];
    return (v00*(1.f-wx) + v01*wx)*(1.f-wy) + (v10*(1.f-wx) + v11*wx)*wy;
}

// ===========================================================================
// K3: fused FEA edges + DoG + combine -> z (split to bf16 hi/lo)
// ===========================================================================
__global__ void k_fuse(const float* __restrict__ wfea) {
    int idx = blockIdx.x * blockDim.x + threadIdx.x;
    if (idx >= NELEM) return;
    int w = idx % WW;
    int h = (idx / WW) % HH;
    int bc = idx / HWP;
    int c = bc % CC;

    const float* yp = g_y + (size_t)bc * HWP;
    float yc = yp[h*WW + w];

    float dC = g_dogk[c*3+0], dE = g_dogk[c*3+1], dX = g_dogk[c*3+2];
    bool hu = h > 0, hd = h < HH-1, wl = w > 0, wr = w < WW-1;
    float nU = hu ? yp[(h-1)*WW + w] : 0.f;
    float nD = hd ? yp[(h+1)*WW + w] : 0.f;
    float nL = wl ? yp[h*WW + (w-1)] : 0.f;
    float nR = wr ? yp[h*WW + (w+1)] : 0.f;
    float c00 = (hu && wl) ? yp[(h-1)*WW + (w-1)] : 0.f;
    float c01 = (hu && wr) ? yp[(h-1)*WW + (w+1)] : 0.f;
    float c10 = (hd && wl) ? yp[(h+1)*WW + (w-1)] : 0.f;
    float c11 = (hd && wr) ? yp[(h+1)*WW + (w+1)] : 0.f;
    float dog = dC*yc + dE*(nU+nD+nL+nR) + dX*(c00+c01+c10+c11);

    const float* p0 = g_d0 + (size_t)bc * (S0*S0);
    const float* p1 = g_d1 + (size_t)bc * (S1*S1);
    const float* p2 = g_d2 + (size_t)bc * (S2*S2);
    float fy0 = fmaxf((h + 0.5f) * (S0/96.f) - 0.5f, 0.f);
    float fx0 = fmaxf((w + 0.5f) * (S0/96.f) - 0.5f, 0.f);
    float fy1 = fmaxf((h + 0.5f) * (S1/96.f) - 0.5f, 0.f);
    float fx1 = fmaxf((w + 0.5f) * (S1/96.f) - 0.5f, 0.f);
    float fy2 = fmaxf((h + 0.5f) * (S2/96.f) - 0.5f, 0.f);
    float fx2 = fmaxf((w + 0.5f) * (S2/96.f) - 0.5f, 0.f);
    float e0 = fabsf(yc - up_bilin(p0, S0, fy0, fx0));
    float e1 = fabsf(yc - up_bilin(p1, S1, fy1, fx1));
    float e2 = fabsf(yc - up_bilin(p2, S2, fy2, fx2));
    float wedge = (fabsf(e0-e1) + fabsf(e0-e2) + fabsf(e1-e2)) * (1.f/3.f);

    float v = 3.f*yc + wfea[c]*wedge + dog;
    __nv_bfloat16 hv = __float2bfloat16(v);
    g_zh[idx] = hv;
    g_zl[idx] = __float2bfloat16(v - __bfloat162float(hv));
}

// ===========================================================================
// K4: HMMA split-bf16 GEMM: out[b,co,n] = sum_ci W[co,ci]*Z[b,ci,n] + skip
//   CTA: 128(M) x 128(N), K=256 in 8 chunks of 32, double-buffered cp.async.
//   8 warps (2 M x 4 N), warp tile 64x32, mma.m16n8k16 bf16 -> f32.
// SMEM per buffer: A[hl]: 128 rows x 80B (32 bf16 + pad)  = 10240B x2
//                  B[hl]: 32 rows x 256B, XOR-swizzled     =  8192B x2
// ===========================================================================
#define ABUF_SZ 10240
#define BUF_STRIDE 36864            // 2*10240 + 2*8192
#define GEMM_SMEM (2*BUF_STRIDE)    // 73728

__global__ void __launch_bounds__(256, 2) k_gemm_mma(
        const float* __restrict__ skip, float* __restrict__ out) {
    extern __shared__ char smem_raw[];
    uint32_t sb = smem_u32(smem_raw);

    int t = threadIdx.x, wid = t >> 5, lane = t & 31;
    int wm = wid & 1, wn = wid >> 1;
    int b = blockIdx.z, co0 = blockIdx.y * 128, n0 = blockIdx.x * 128;

    const __nv_bfloat16* whlo[2] = { g_wh, g_wl };
    const __nv_bfloat16* zhlo[2] = { g_zh, g_zl };

    // ---- chunk loader: 2048 x 16B cp.async (8 per thread) ----
    auto load_chunk = [&](int kc, int d) {
        uint32_t base = sb + d * BUF_STRIDE;
#pragma unroll
        for (int j = 0; j < 4; j++) {            // A: hl*128rows*4chunks
            int idx = j * 256 + t;
            int hl = idx >> 9, rem = idx & 511;
            int row = rem >> 2, c = rem & 3;
            const __nv_bfloat16* src = whlo[hl] + (co0 + row) * CC + kc * 32 + c * 8;
            CP16(base + hl * ABUF_SZ + row * 80 + c * 16, src);
        }
#pragma unroll
        for (int j = 0; j < 4; j++) {            // B: hl*32rows*16chunks
            int idx = j * 256 + t;
            int hl = idx >> 9, rem = idx & 511;
            int row = rem >> 4, c = rem & 15;
            const __nv_bfloat16* src = zhlo[hl]
                + (size_t)(b * CC + kc * 32 + row) * HWP + n0 + c * 8;
            CP16(base + 2 * ABUF_SZ + hl * 8192 + row * 256
                 + (uint32_t)((c ^ (row & 7)) << 4), src);
        }
    };

    float acc[4][4][4];
#pragma unroll
    for (int i = 0; i < 4; i++)
#pragma unroll
        for (int j = 0; j < 4; j++)
#pragma unroll
            for (int k = 0; k < 4; k++) acc[i][j][k] = 0.f;

    // ldmatrix lane-address components
    int lt = lane >> 3;                  // subtile 0..3
    int lrA = (lane & 7) + ((lt & 1) << 3);      // A row within 16
    int lcA = (lt >> 1) << 4;                    // A col bytes within k16
    int lkB = (lane & 7) + ((lt & 1) << 3);      // B k-row within 16
    int lnB = (lt >> 1) << 3;                    // B n offset within 16

    load_chunk(0, 0);
    CP_COMMIT();

    for (int kc = 0; kc < 8; kc++) {
        int d = kc & 1;
        if (kc + 1 < 8) { load_chunk(kc + 1, d ^ 1); CP_COMMIT(); CP_WAIT1(); }
        else           { CP_WAIT0(); }
        __syncthreads();

        uint32_t abase = sb + d * BUF_STRIDE;
        uint32_t bbase = abase + 2 * ABUF_SZ;

#pragma unroll
        for (int ks = 0; ks < 2; ks++) {
            // A fragments (hi & lo) for 4 m-tiles
            uint32_t ah[4][4], al[4][4];
#pragma unroll
            for (int mi = 0; mi < 4; mi++) {
                uint32_t arow = (uint32_t)(wm * 64 + mi * 16 + lrA);
                ldsm_x4(ah[mi], abase + arow * 80 + ks * 32 + lcA);
                ldsm_x4(al[mi], abase + ABUF_SZ + arow * 80 + ks * 32 + lcA);
            }
#pragma unroll
            for (int np = 0; np < 2; np++) {     // n-pairs of 16
                uint32_t krow = (uint32_t)(ks * 16 + lkB);
                uint32_t nb   = (uint32_t)(wn * 32 + np * 16 + lnB);
                uint32_t chunk = nb >> 3;
                uint32_t swz = (chunk ^ (krow & 7)) << 4;
                uint32_t bh[4], bl[4];
                ldsm_x4_t(bh, bbase + krow * 256 + swz);
                ldsm_x4_t(bl, bbase + 8192 + krow * 256 + swz);
#pragma unroll
                for (int mi = 0; mi < 4; mi++) {
                    mma_bf16(acc[mi][np*2+0], ah[mi], bh + 0);
                    mma_bf16(acc[mi][np*2+1], ah[mi], bh + 2);
                    mma_bf16(acc[mi][np*2+0], ah[mi], bl + 0);
                    mma_bf16(acc[mi][np*2+1], ah[mi], bl + 2);
                    mma_bf16(acc[mi][np*2+0], al[mi], bh + 0);
                    mma_bf16(acc[mi][np*2+1], al[mi], bh + 2);
                }
            }
        }
        __syncthreads();
    }

    // ---- epilogue: direct stores with skip residual ----
    int er = lane >> 2, ec = (lane & 3) * 2;
#pragma unroll
    for (int mi = 0; mi < 4; mi++) {
#pragma unroll
        for (int ni = 0; ni < 4; ni++) {
            int row = co0 + wm * 64 + mi * 16 + er;
            int col = n0 + wn * 32 + ni * 8 + ec;
            size_t g0 = (size_t)(b * CC + row) * HWP + col;
            size_t g1 = g0 + 8 * HWP;
            float2 s0 = *(const float2*)(skip + g0);
            float2 s1 = *(const float2*)(skip + g1);
            float2 o0 = make_float2(acc[mi][ni][0] + s0.x, acc[mi][ni][1] + s0.y);
            float2 o1 = make_float2(acc[mi][ni][2] + s1.x, acc[mi][ni][3] + s1.y);
            *(float2*)(out + g0) = o0;
            *(float2*)(out + g1) = o1;
        }
    }
}

// ===========================================================================
extern "C" void kernel_launch(void* const* d_in, const int* in_sizes, int n_in,
                              void* d_out, int out_size) {
    const float* skip   = (const float*)d_in[0];
    const float* dec    = (const float*)d_in[1];
    const float* w_fea  = (const float*)d_in[2];
    const float* sigma1 = (const float*)d_in[3];
    const float* sigma2 = (const float*)d_in[4];
    const float* mixerw = (const float*)d_in[5];
    float* out = (float*)d_out;

    float* yg; cudaGetSymbolAddress((void**)&yg, g_y);
    float* d0; cudaGetSymbolAddress((void**)&d0, g_d0);
    float* d1; cudaGetSymbolAddress((void**)&d1, g_d1);
    float* d2; cudaGetSymbolAddress((void**)&d2, g_d2);

    k_params<<<1, CC>>>(sigma1, sigma2);
    k_wsplit<<<CC*CC/256, 256>>>(mixerw);

    int n4 = NELEM / 4;
    k_add<<<(n4 + 255) / 256, 256>>>((const float4*)dec, (const float4*)skip,
                                     (float4*)yg, n4);

    { int t0 = BB*CC*S0*S0; k_down<<<(t0 + 255)/256, 256>>>(yg, d0, S0, 96.f/S0, t0); }
    { int t1 = BB*CC*S1*S1; k_down<<<(t1 + 255)/256, 256>>>(yg, d1, S1, 96.f/S1, t1); }
    { int t2 = BB*CC*S2*S2; k_down<<<(t2 + 255)/256, 256>>>(yg, d2, S2, 96.f/S2, t2); }

    k_fuse<<<NELEM / 256, 256>>>(w_fea);

    cudaFuncSetAttribute(k_gemm_mma, cudaFuncAttributeMaxDynamicSharedMemorySize,
                         GEMM_SMEM);
    dim3 grid(HWP / 128, CC / 128, BB);
    k_gemm_mma<<<grid, 256, GEMM_SMEM>>>(skip, out);
}

// round 4
// speedup vs baseline: 2.2054x; 1.4977x over previous
#include <cuda_runtime.h>
#include <cuda_bf16.h>
#include <math.h>
#include <stdint.h>

// ---- problem constants ----
#define BB 16
#define CC 256
#define HH 96
#define WW 96
#define HWP (HH*WW)                 // 9216
#define NELEM (BB*CC*HWP)           // 37748736
#define S0 24
#define S1 48
#define S2 72

// ---- scratch (device globals: allocation-free rule) ----
__device__ __nv_bfloat16 g_zh[NELEM];
__device__ __nv_bfloat16 g_zl[NELEM];
__device__ __nv_bfloat16 g_wh[CC*CC];
__device__ __nv_bfloat16 g_wl[CC*CC];
__device__ float g_dogk[CC*3];

// ===========================================================================
// PTX helpers (family-portable: ldmatrix / mma.sync / cp.async only)
// ===========================================================================
__device__ __forceinline__ uint32_t smem_u32(const void* p) {
    uint32_t a;
    asm("{ .reg .u64 t; cvta.to.shared.u64 t, %1; cvt.u32.u64 %0, t; }"
        : "=r"(a) : "l"(p));
    return a;
}
#define CP16(dst, src) asm volatile( \
    "cp.async.cg.shared.global [%0], [%1], 16;" :: "r"(dst), "l"(src) : "memory")
#define CP_COMMIT() asm volatile("cp.async.commit_group;" ::: "memory")
#define CP_WAIT1() asm volatile("cp.async.wait_group 1;" ::: "memory")
#define CP_WAIT0() asm volatile("cp.async.wait_group 0;" ::: "memory")

__device__ __forceinline__ void ldsm_x4(uint32_t* r, uint32_t addr) {
    asm volatile("ldmatrix.sync.aligned.m8n8.x4.shared.b16 {%0,%1,%2,%3}, [%4];"
                 : "=r"(r[0]), "=r"(r[1]), "=r"(r[2]), "=r"(r[3]) : "r"(addr));
}
__device__ __forceinline__ void ldsm_x4_t(uint32_t* r, uint32_t addr) {
    asm volatile("ldmatrix.sync.aligned.m8n8.x4.trans.shared.b16 {%0,%1,%2,%3}, [%4];"
                 : "=r"(r[0]), "=r"(r[1]), "=r"(r[2]), "=r"(r[3]) : "r"(addr));
}
__device__ __forceinline__ void mma_bf16(float* c, const uint32_t* a, const uint32_t* b) {
    asm volatile(
        "mma.sync.aligned.m16n8k16.row.col.f32.bf16.bf16.f32 "
        "{%0,%1,%2,%3}, {%4,%5,%6,%7}, {%8,%9}, {%0,%1,%2,%3};"
        : "+f"(c[0]), "+f"(c[1]), "+f"(c[2]), "+f"(c[3])
        : "r"(a[0]), "r"(a[1]), "r"(a[2]), "r"(a[3]), "r"(b[0]), "r"(b[1]));
}

// ===========================================================================
// K0: per-channel DoG difference-kernel coefficients
// ===========================================================================
__global__ void k_params(const float* __restrict__ s1r, const float* __restrict__ s2r) {
    int c = threadIdx.x;
    float s1 = 2.f / (1.f + expf(-s1r[c]));
    float s2 = 2.f / (1.f + expf(-s2r[c]));
    float e1 = expf(-1.f / (2.f * s1 * s1)); float q1 = expf(-1.f / (s1 * s1));
    float e2 = expf(-1.f / (2.f * s2 * s2)); float q2 = expf(-1.f / (s2 * s2));
    float n1 = 1.f + 4.f * e1 + 4.f * q1;
    float n2 = 1.f + 4.f * e2 + 4.f * q2;
    g_dogk[c*3+0] = 1.f/n1 - 1.f/n2;
    g_dogk[c*3+1] = e1/n1 - e2/n2;
    g_dogk[c*3+2] = q1/n1 - q2/n2;
}

// K0b: split mixer weight into bf16 hi/lo
__global__ void k_wsplit(const float* __restrict__ w) {
    int i = blockIdx.x * 256 + threadIdx.x;
    float v = w[i];
    __nv_bfloat16 h = __float2bfloat16(v);
    g_wh[i] = h;
    g_wl[i] = __float2bfloat16(v - __bfloat162float(h));
}

// ===========================================================================
// K1: fused per-plane elementwise chain.
//  One CTA per (b,c) plane. SMEM: y[9216] fp32 + pyramid d0/d1/d2 [8064] fp32.
//  dec+skip -> y (smem) -> downsamples (smem) -> edges+DoG -> zh/zl (global).
// ===========================================================================
#define SMF_Y  0
#define SMF_D0 9216
#define SMF_D1 (9216+576)
#define SMF_D2 (9216+2880)
#define PLANE_SMEM ((9216+8064)*4)   // 69120 B

__device__ __forceinline__ float bilin_sm(const float* __restrict__ p, int S,
                                          float fy, float fx) {
    int y0 = (int)fy, x0 = (int)fx;
    float wy = fy - y0, wx = fx - x0;
    int y1 = min(y0 + 1, S - 1), x1 = min(x0 + 1, S - 1);
    float v00 = p[y0*S + x0], v01 = p[y0*S + x1];
    float v10 = p[y1*S + x0], v11 = p[y1*S + x1];
    return (v00*(1.f-wx) + v01*wx)*(1.f-wy) + (v10*(1.f-wx) + v11*wx)*wy;
}

__global__ void __launch_bounds__(256) k_plane(const float4* __restrict__ dec,
                                               const float4* __restrict__ skip,
                                               const float* __restrict__ wfea) {
    extern __shared__ float sm[];
    int bc = blockIdx.x;
    int c  = bc % CC;
    int t  = threadIdx.x;

    // 1) y = dec + skip into smem (float4, coalesced)
    const float4* dp = dec  + (size_t)bc * (HWP/4);
    const float4* sp = skip + (size_t)bc * (HWP/4);
    float4* y4 = (float4*)(sm + SMF_Y);
#pragma unroll
    for (int k = 0; k < 9; k++) {
        int i = k * 256 + t;
        float4 a = dp[i], b = sp[i];
        y4[i] = make_float4(a.x + b.x, a.y + b.y, a.z + b.z, a.w + b.w);
    }
    __syncthreads();

    const float* sy = sm + SMF_Y;

    // 2) three bilinear downsamples into smem (8064 outputs)
    for (int k = 0; k < 32; k++) {
        int i = k * 256 + t;
        if (i >= 8064) break;
        int S, off, o;
        if (i < 576)       { S = S0; off = SMF_D0; o = i; }
        else if (i < 2880) { S = S1; off = SMF_D1; o = i - 576; }
        else               { S = S2; off = SMF_D2; o = i - 2880; }
        int oy = o / S, ox = o % S;
        float sf = 96.f / S;
        float fy = fmaxf((oy + 0.5f) * sf - 0.5f, 0.f);
        float fx = fmaxf((ox + 0.5f) * sf - 0.5f, 0.f);
        int y0 = (int)fy, x0 = (int)fx;
        float wy = fy - y0, wx = fx - x0;
        int y1 = min(y0 + 1, HH - 1), x1 = min(x0 + 1, WW - 1);
        float v00 = sy[y0*WW + x0], v01 = sy[y0*WW + x1];
        float v10 = sy[y1*WW + x0], v11 = sy[y1*WW + x1];
        sm[off + o] = (v00*(1.f-wx) + v01*wx)*(1.f-wy) + (v10*(1.f-wx) + v11*wx)*wy;
    }
    __syncthreads();

    // 3) fused edges + DoG + combine -> zh/zl
    float dC = g_dogk[c*3+0], dE = g_dogk[c*3+1], dX = g_dogk[c*3+2];
    float wf = wfea[c];
    const float* p0 = sm + SMF_D0;
    const float* p1 = sm + SMF_D1;
    const float* p2 = sm + SMF_D2;
    size_t gbase = (size_t)bc * HWP;

#pragma unroll
    for (int k = 0; k < 36; k++) {
        int i = k * 256 + t;
        int w = i % WW, h = i / WW;
        float yc = sy[i];

        bool hu = h > 0, hd = h < HH-1, wl = w > 0, wr = w < WW-1;
        float nU = hu ? sy[i - WW] : 0.f;
        float nD = hd ? sy[i + WW] : 0.f;
        float nL = wl ? sy[i - 1]  : 0.f;
        float nR = wr ? sy[i + 1]  : 0.f;
        float c00 = (hu && wl) ? sy[i - WW - 1] : 0.f;
        float c01 = (hu && wr) ? sy[i - WW + 1] : 0.f;
        float c10 = (hd && wl) ? sy[i + WW - 1] : 0.f;
        float c11 = (hd && wr) ? sy[i + WW + 1] : 0.f;
        float dog = dC*yc + dE*(nU+nD+nL+nR) + dX*(c00+c01+c10+c11);

        float fy0 = fmaxf((h + 0.5f) * (S0/96.f) - 0.5f, 0.f);
        float fx0 = fmaxf((w + 0.5f) * (S0/96.f) - 0.5f, 0.f);
        float fy1 = fmaxf((h + 0.5f) * (S1/96.f) - 0.5f, 0.f);
        float fx1 = fmaxf((w + 0.5f) * (S1/96.f) - 0.5f, 0.f);
        float fy2 = fmaxf((h + 0.5f) * (S2/96.f) - 0.5f, 0.f);
        float fx2 = fmaxf((w + 0.5f) * (S2/96.f) - 0.5f, 0.f);
        float e0 = fabsf(yc - bilin_sm(p0, S0, fy0, fx0));
        float e1 = fabsf(yc - bilin_sm(p1, S1, fy1, fx1));
        float e2 = fabsf(yc - bilin_sm(p2, S2, fy2, fx2));
        float wedge = (fabsf(e0-e1) + fabsf(e0-e2) + fabsf(e1-e2)) * (1.f/3.f);

        float v = 3.f*yc + wf*wedge + dog;
        __nv_bfloat16 hv = __float2bfloat16(v);
        g_zh[gbase + i] = hv;
        g_zl[gbase + i] = __float2bfloat16(v - __bfloat162float(hv));
    }
}

// ===========================================================================
// K4: HMMA split-bf16 GEMM: out[b,co,n] = sum_ci W[co,ci]*Z[b,ci,n] + skip
//   CTA: 128(M) x 128(N), K=256 in 8 chunks of 32, double-buffered cp.async.
//   8 warps (2 M x 4 N), warp tile 64x32, mma.m16n8k16 bf16 -> f32.
// ===========================================================================
#define ABUF_SZ 10240
#define BUF_STRIDE 36864            // 2*10240 + 2*8192
#define GEMM_SMEM (2*BUF_STRIDE)    // 73728

__global__ void __launch_bounds__(256, 2) k_gemm_mma(
        const float* __restrict__ skip, float* __restrict__ out) {
    extern __shared__ char smem_raw[];
    uint32_t sb = smem_u32(smem_raw);

    int t = threadIdx.x, wid = t >> 5, lane = t & 31;
    int wm = wid & 1, wn = wid >> 1;
    int b = blockIdx.z, co0 = blockIdx.y * 128, n0 = blockIdx.x * 128;

    const __nv_bfloat16* whlo[2] = { g_wh, g_wl };
    const __nv_bfloat16* zhlo[2] = { g_zh, g_zl };

    auto load_chunk = [&](int kc, int d) {
        uint32_t base = sb + d * BUF_STRIDE;
#pragma unroll
        for (int j = 0; j < 4; j++) {            // A: hl*128rows*4chunks
            int idx = j * 256 + t;
            int hl = idx >> 9, rem = idx & 511;
            int row = rem >> 2, c = rem & 3;
            const __nv_bfloat16* src = whlo[hl] + (co0 + row) * CC + kc * 32 + c * 8;
            CP16(base + hl * ABUF_SZ + row * 80 + c * 16, src);
        }
#pragma unroll
        for (int j = 0; j < 4; j++) {            // B: hl*32rows*16chunks
            int idx = j * 256 + t;
            int hl = idx >> 9, rem = idx & 511;
            int row = rem >> 4, c = rem & 15;
            const __nv_bfloat16* src = zhlo[hl]
                + (size_t)(b * CC + kc * 32 + row) * HWP + n0 + c * 8;
            CP16(base + 2 * ABUF_SZ + hl * 8192 + row * 256
                 + (uint32_t)((c ^ (row & 7)) << 4), src);
        }
    };

    float acc[4][4][4];
#pragma unroll
    for (int i = 0; i < 4; i++)
#pragma unroll
        for (int j = 0; j < 4; j++)
#pragma unroll
            for (int k = 0; k < 4; k++) acc[i][j][k] = 0.f;

    int lt = lane >> 3;
    int lrA = (lane & 7) + ((lt & 1) << 3);
    int lcA = (lt >> 1) << 4;
    int lkB = (lane & 7) + ((lt & 1) << 3);
    int lnB = (lt >> 1) << 3;

    load_chunk(0, 0);
    CP_COMMIT();

    for (int kc = 0; kc < 8; kc++) {
        int d = kc & 1;
        if (kc + 1 < 8) { load_chunk(kc + 1, d ^ 1); CP_COMMIT(); CP_WAIT1(); }
        else           { CP_WAIT0(); }
        __syncthreads();

        uint32_t abase = sb + d * BUF_STRIDE;
        uint32_t bbase = abase + 2 * ABUF_SZ;

#pragma unroll
        for (int ks = 0; ks < 2; ks++) {
            uint32_t ah[4][4], al[4][4];
#pragma unroll
            for (int mi = 0; mi < 4; mi++) {
                uint32_t arow = (uint32_t)(wm * 64 + mi * 16 + lrA);
                ldsm_x4(ah[mi], abase + arow * 80 + ks * 32 + lcA);
                ldsm_x4(al[mi], abase + ABUF_SZ + arow * 80 + ks * 32 + lcA);
            }
#pragma unroll
            for (int np = 0; np < 2; np++) {
                uint32_t krow = (uint32_t)(ks * 16 + lkB);
                uint32_t nb   = (uint32_t)(wn * 32 + np * 16 + lnB);
                uint32_t chunk = nb >> 3;
                uint32_t swz = (chunk ^ (krow & 7)) << 4;
                uint32_t bh[4], bl[4];
                ldsm_x4_t(bh, bbase + krow * 256 + swz);
                ldsm_x4_t(bl, bbase + 8192 + krow * 256 + swz);
#pragma unroll
                for (int mi = 0; mi < 4; mi++) {
                    mma_bf16(acc[mi][np*2+0], ah[mi], bh + 0);
                    mma_bf16(acc[mi][np*2+1], ah[mi], bh + 2);
                    mma_bf16(acc[mi][np*2+0], ah[mi], bl + 0);
                    mma_bf16(acc[mi][np*2+1], ah[mi], bl + 2);
                    mma_bf16(acc[mi][np*2+0], al[mi], bh + 0);
                    mma_bf16(acc[mi][np*2+1], al[mi], bh + 2);
                }
            }
        }
        __syncthreads();
    }

    int er = lane >> 2, ec = (lane & 3) * 2;
#pragma unroll
    for (int mi = 0; mi < 4; mi++) {
#pragma unroll
        for (int ni = 0; ni < 4; ni++) {
            int row = co0 + wm * 64 + mi * 16 + er;
            int col = n0 + wn * 32 + ni * 8 + ec;
            size_t g0 = (size_t)(b * CC + row) * HWP + col;
            size_t g1 = g0 + 8 * HWP;
            float2 s0 = *(const float2*)(skip + g0);
            float2 s1 = *(const float2*)(skip + g1);
            float2 o0 = make_float2(acc[mi][ni][0] + s0.x, acc[mi][ni][1] + s0.y);
            float2 o1 = make_float2(acc[mi][ni][2] + s1.x, acc[mi][ni][3] + s1.y);
            *(float2*)(out + g0) = o0;
            *(float2*)(out + g1) = o1;
        }
    }
}

// ===========================================================================
extern "C" void kernel_launch(void* const* d_in, const int* in_sizes, int n_in,
                              void* d_out, int out_size) {
    const float* skip   = (const float*)d_in[0];
    const float* dec    = (const float*)d_in[1];
    const float* w_fea  = (const float*)d_in[2];
    const float* sigma1 = (const float*)d_in[3];
    const float* sigma2 = (const float*)d_in[4];
    const float* mixerw = (const float*)d_in[5];
    float* out = (float*)d_out;

    k_params<<<1, CC>>>(sigma1, sigma2);
    k_wsplit<<<CC*CC/256, 256>>>(mixerw);

    cudaFuncSetAttribute(k_plane, cudaFuncAttributeMaxDynamicSharedMemorySize,
                         PLANE_SMEM);
    k_plane<<<BB*CC, 256, PLANE_SMEM>>>((const float4*)dec, (const float4*)skip,
                                        w_fea);

    cudaFuncSetAttribute(k_gemm_mma, cudaFuncAttributeMaxDynamicSharedMemorySize,
                         GEMM_SMEM);
    dim3 grid(HWP / 128, CC / 128, BB);
    k_gemm_mma<<<grid, 256, GEMM_SMEM>>>(skip, out);
}

// round 5
// speedup vs baseline: 2.4188x; 1.0967x over previous
#include <cuda_runtime.h>
#include <cuda_bf16.h>
#include <math.h>
#include <stdint.h>

// ---- problem constants ----
#define BB 16
#define CC 256
#define HH 96
#define WW 96
#define HWP (HH*WW)                 // 9216
#define NELEM (BB*CC*HWP)           // 37748736
#define S0 24
#define S1 48
#define S2 72

// ---- scratch (device globals: allocation-free rule) ----
__device__ __nv_bfloat16 g_zh[NELEM];
__device__ __nv_bfloat16 g_zl[NELEM];
__device__ __nv_bfloat16 g_wh[CC*CC];
__device__ __nv_bfloat16 g_wl[CC*CC];
__device__ float g_dogk[CC*3];

// ===========================================================================
// PTX helpers (family-portable: ldmatrix / mma.sync / cp.async only)
// ===========================================================================
__device__ __forceinline__ uint32_t smem_u32(const void* p) {
    uint32_t a;
    asm("{ .reg .u64 t; cvta.to.shared.u64 t, %1; cvt.u32.u64 %0, t; }"
        : "=r"(a) : "l"(p));
    return a;
}
#define CP16(dst, src) asm volatile( \
    "cp.async.cg.shared.global [%0], [%1], 16;" :: "r"(dst), "l"(src) : "memory")
#define CP_COMMIT() asm volatile("cp.async.commit_group;" ::: "memory")
#define CP_WAIT1() asm volatile("cp.async.wait_group 1;" ::: "memory")
#define CP_WAIT0() asm volatile("cp.async.wait_group 0;" ::: "memory")

__device__ __forceinline__ void ldsm_x4(uint32_t* r, uint32_t addr) {
    asm volatile("ldmatrix.sync.aligned.m8n8.x4.shared.b16 {%0,%1,%2,%3}, [%4];"
                 : "=r"(r[0]), "=r"(r[1]), "=r"(r[2]), "=r"(r[3]) : "r"(addr));
}
__device__ __forceinline__ void ldsm_x4_t(uint32_t* r, uint32_t addr) {
    asm volatile("ldmatrix.sync.aligned.m8n8.x4.trans.shared.b16 {%0,%1,%2,%3}, [%4];"
                 : "=r"(r[0]), "=r"(r[1]), "=r"(r[2]), "=r"(r[3]) : "r"(addr));
}
__device__ __forceinline__ void mma_bf16(float* c, const uint32_t* a, const uint32_t* b) {
    asm volatile(
        "mma.sync.aligned.m16n8k16.row.col.f32.bf16.bf16.f32 "
        "{%0,%1,%2,%3}, {%4,%5,%6,%7}, {%8,%9}, {%0,%1,%2,%3};"
        : "+f"(c[0]), "+f"(c[1]), "+f"(c[2]), "+f"(c[3])
        : "r"(a[0]), "r"(a[1]), "r"(a[2]), "r"(a[3]), "r"(b[0]), "r"(b[1]));
}

// ===========================================================================
// K0: per-channel DoG difference-kernel coefficients
// ===========================================================================
__global__ void k_params(const float* __restrict__ s1r, const float* __restrict__ s2r) {
    int c = threadIdx.x;
    float s1 = 2.f / (1.f + expf(-s1r[c]));
    float s2 = 2.f / (1.f + expf(-s2r[c]));
    float e1 = expf(-1.f / (2.f * s1 * s1)); float q1 = expf(-1.f / (s1 * s1));
    float e2 = expf(-1.f / (2.f * s2 * s2)); float q2 = expf(-1.f / (s2 * s2));
    float n1 = 1.f + 4.f * e1 + 4.f * q1;
    float n2 = 1.f + 4.f * e2 + 4.f * q2;
    g_dogk[c*3+0] = 1.f/n1 - 1.f/n2;
    g_dogk[c*3+1] = e1/n1 - e2/n2;
    g_dogk[c*3+2] = q1/n1 - q2/n2;
}

// K0b: split mixer weight into bf16 hi/lo
__global__ void k_wsplit(const float* __restrict__ w) {
    int i = blockIdx.x * 256 + threadIdx.x;
    float v = w[i];
    __nv_bfloat16 h = __float2bfloat16(v);
    g_wh[i] = h;
    g_wl[i] = __float2bfloat16(v - __bfloat162float(h));
}

// ===========================================================================
// K1: fused per-plane elementwise chain. One CTA / (b,c) plane, 512 threads.
// ===========================================================================
#define SMF_Y  0
#define SMF_D0 9216
#define SMF_D1 (9216+576)
#define SMF_D2 (9216+2880)
#define PLANE_SMEM ((9216+8064)*4)   // 69120 B
#define PT 512

__device__ __forceinline__ float bilin_sm(const float* __restrict__ p, int S,
                                          float fy, float fx) {
    int y0 = (int)fy, x0 = (int)fx;
    float wy = fy - y0, wx = fx - x0;
    int y1 = min(y0 + 1, S - 1), x1 = min(x0 + 1, S - 1);
    float v00 = p[y0*S + x0], v01 = p[y0*S + x1];
    float v10 = p[y1*S + x0], v11 = p[y1*S + x1];
    return (v00*(1.f-wx) + v01*wx)*(1.f-wy) + (v10*(1.f-wx) + v11*wx)*wy;
}

__device__ __forceinline__ float plane_val(const float* __restrict__ sy,
                                           const float* __restrict__ p0,
                                           const float* __restrict__ p1,
                                           const float* __restrict__ p2,
                                           float dC, float dE, float dX, float wf,
                                           int i) {
    int w = i % WW, h = i / WW;
    float yc = sy[i];

    bool hu = h > 0, hd = h < HH-1, wl = w > 0, wr = w < WW-1;
    float nU = hu ? sy[i - WW] : 0.f;
    float nD = hd ? sy[i + WW] : 0.f;
    float nL = wl ? sy[i - 1]  : 0.f;
    float nR = wr ? sy[i + 1]  : 0.f;
    float c00 = (hu && wl) ? sy[i - WW - 1] : 0.f;
    float c01 = (hu && wr) ? sy[i - WW + 1] : 0.f;
    float c10 = (hd && wl) ? sy[i + WW - 1] : 0.f;
    float c11 = (hd && wr) ? sy[i + WW + 1] : 0.f;
    float dog = dC*yc + dE*(nU+nD+nL+nR) + dX*(c00+c01+c10+c11);

    float fy0 = fmaxf((h + 0.5f) * (S0/96.f) - 0.5f, 0.f);
    float fx0 = fmaxf((w + 0.5f) * (S0/96.f) - 0.5f, 0.f);
    float fy1 = fmaxf((h + 0.5f) * (S1/96.f) - 0.5f, 0.f);
    float fx1 = fmaxf((w + 0.5f) * (S1/96.f) - 0.5f, 0.f);
    float fy2 = fmaxf((h + 0.5f) * (S2/96.f) - 0.5f, 0.f);
    float fx2 = fmaxf((w + 0.5f) * (S2/96.f) - 0.5f, 0.f);
    float e0 = fabsf(yc - bilin_sm(p0, S0, fy0, fx0));
    float e1 = fabsf(yc - bilin_sm(p1, S1, fy1, fx1));
    float e2 = fabsf(yc - bilin_sm(p2, S2, fy2, fx2));
    float wedge = (fabsf(e0-e1) + fabsf(e0-e2) + fabsf(e1-e2)) * (1.f/3.f);

    return 3.f*yc + wf*wedge + dog;
}

__global__ void __launch_bounds__(PT) k_plane(const float4* __restrict__ dec,
                                              const float4* __restrict__ skip,
                                              const float* __restrict__ wfea) {
    extern __shared__ float sm[];
    int bc = blockIdx.x;
    int c  = bc % CC;
    int t  = threadIdx.x;

    // 1) y = dec + skip into smem
    const float4* dp = dec  + (size_t)bc * (HWP/4);
    const float4* sp = skip + (size_t)bc * (HWP/4);
    float4* y4 = (float4*)(sm + SMF_Y);
#pragma unroll
    for (int k = 0; k < 5; k++) {
        int i = k * PT + t;
        if (i < HWP/4) {
            float4 a = dp[i], b = sp[i];
            y4[i] = make_float4(a.x + b.x, a.y + b.y, a.z + b.z, a.w + b.w);
        }
    }
    __syncthreads();

    const float* sy = sm + SMF_Y;

    // 2) three bilinear downsamples into smem (8064 outputs)
#pragma unroll
    for (int k = 0; k < 16; k++) {
        int i = k * PT + t;
        if (i >= 8064) break;
        int S, off, o;
        if (i < 576)       { S = S0; off = SMF_D0; o = i; }
        else if (i < 2880) { S = S1; off = SMF_D1; o = i - 576; }
        else               { S = S2; off = SMF_D2; o = i - 2880; }
        int oy = o / S, ox = o % S;
        float sf = 96.f / S;
        float fy = fmaxf((oy + 0.5f) * sf - 0.5f, 0.f);
        float fx = fmaxf((ox + 0.5f) * sf - 0.5f, 0.f);
        int y0 = (int)fy, x0 = (int)fx;
        float wy = fy - y0, wx = fx - x0;
        int y1 = min(y0 + 1, HH - 1), x1 = min(x0 + 1, WW - 1);
        float v00 = sy[y0*WW + x0], v01 = sy[y0*WW + x1];
        float v10 = sy[y1*WW + x0], v11 = sy[y1*WW + x1];
        sm[off + o] = (v00*(1.f-wx) + v01*wx)*(1.f-wy) + (v10*(1.f-wx) + v11*wx)*wy;
    }
    __syncthreads();

    // 3) fused edges + DoG + combine -> zh/zl (paired bf16x2 stores)
    float dC = g_dogk[c*3+0], dE = g_dogk[c*3+1], dX = g_dogk[c*3+2];
    float wf = wfea[c];
    const float* p0 = sm + SMF_D0;
    const float* p1 = sm + SMF_D1;
    const float* p2 = sm + SMF_D2;
    size_t gbase = (size_t)bc * HWP;
    uint32_t* zh2 = (uint32_t*)(g_zh + gbase);
    uint32_t* zl2 = (uint32_t*)(g_zl + gbase);

#pragma unroll
    for (int k = 0; k < 9; k++) {
        int j = k * PT + t;          // pair index, i = 2j (rows are even-width)
        int i = 2 * j;
        float v0 = plane_val(sy, p0, p1, p2, dC, dE, dX, wf, i);
        float v1 = plane_val(sy, p0, p1, p2, dC, dE, dX, wf, i + 1);
        __nv_bfloat16 h0 = __float2bfloat16(v0);
        __nv_bfloat16 h1 = __float2bfloat16(v1);
        __nv_bfloat16 l0 = __float2bfloat16(v0 - __bfloat162float(h0));
        __nv_bfloat16 l1 = __float2bfloat16(v1 - __bfloat162float(h1));
        uint32_t hp = ((uint32_t)__bfloat16_as_ushort(h1) << 16)
                    |  (uint32_t)__bfloat16_as_ushort(h0);
        uint32_t lp = ((uint32_t)__bfloat16_as_ushort(l1) << 16)
                    |  (uint32_t)__bfloat16_as_ushort(l0);
        zh2[j] = hp;
        zl2[j] = lp;
    }
}

// ===========================================================================
// K4: HMMA split-bf16 GEMM, 3-stage cp.async pipeline, 1 sync per chunk.
//   CTA: 128(M) x 128(N), K=256 in 8 chunks of 32.
//   8 warps (2 M x 4 N), warp tile 64x32, mma.m16n8k16 bf16 -> f32.
// ===========================================================================
#define ABUF_SZ 10240
#define BUF_STRIDE 36864            // 2*10240 + 2*8192
#define NSTAGE 3
#define GEMM_SMEM (NSTAGE*BUF_STRIDE)  // 110592

__global__ void __launch_bounds__(256, 2) k_gemm_mma(
        const float* __restrict__ skip, float* __restrict__ out) {
    extern __shared__ char smem_raw[];
    uint32_t sb = smem_u32(smem_raw);

    int t = threadIdx.x, wid = t >> 5, lane = t & 31;
    int wm = wid & 1, wn = wid >> 1;
    int b = blockIdx.z, co0 = blockIdx.y * 128, n0 = blockIdx.x * 128;

    const __nv_bfloat16* whlo[2] = { g_wh, g_wl };
    const __nv_bfloat16* zhlo[2] = { g_zh, g_zl };

    auto load_chunk = [&](int kc, int d) {
        uint32_t base = sb + (uint32_t)d * BUF_STRIDE;
#pragma unroll
        for (int j = 0; j < 4; j++) {            // A
            int idx = j * 256 + t;
            int hl = idx >> 9, rem = idx & 511;
            int row = rem >> 2, c = rem & 3;
            const __nv_bfloat16* src = whlo[hl] + (co0 + row) * CC + kc * 32 + c * 8;
            CP16(base + hl * ABUF_SZ + row * 80 + c * 16, src);
        }
#pragma unroll
        for (int j = 0; j < 4; j++) {            // B
            int idx = j * 256 + t;
            int hl = idx >> 9, rem = idx & 511;
            int row = rem >> 4, c = rem & 15;
            const __nv_bfloat16* src = zhlo[hl]
                + (size_t)(b * CC + kc * 32 + row) * HWP + n0 + c * 8;
            CP16(base + 2 * ABUF_SZ + hl * 8192 + row * 256
                 + (uint32_t)((c ^ (row & 7)) << 4), src);
        }
    };

    float acc[4][4][4];
#pragma unroll
    for (int i = 0; i < 4; i++)
#pragma unroll
        for (int j = 0; j < 4; j++)
#pragma unroll
            for (int k = 0; k < 4; k++) acc[i][j][k] = 0.f;

    int lt = lane >> 3;
    int lrA = (lane & 7) + ((lt & 1) << 3);
    int lcA = (lt >> 1) << 4;
    int lkB = (lane & 7) + ((lt & 1) << 3);
    int lnB = (lt >> 1) << 3;

    // prologue: stages 0,1 in flight
    load_chunk(0, 0); CP_COMMIT();
    load_chunk(1, 1); CP_COMMIT();

    for (int kc = 0; kc < 8; kc++) {
        if (kc + 2 < 8) CP_WAIT1(); else CP_WAIT0();
        __syncthreads();
        if (kc + 2 < 8) { load_chunk(kc + 2, (kc + 2) % NSTAGE); CP_COMMIT(); }

        uint32_t abase = sb + (uint32_t)(kc % NSTAGE) * BUF_STRIDE;
        uint32_t bbase = abase + 2 * ABUF_SZ;

#pragma unroll
        for (int ks = 0; ks < 2; ks++) {
            uint32_t ah[4][4], al[4][4];
#pragma unroll
            for (int mi = 0; mi < 4; mi++) {
                uint32_t arow = (uint32_t)(wm * 64 + mi * 16 + lrA);
                ldsm_x4(ah[mi], abase + arow * 80 + ks * 32 + lcA);
                ldsm_x4(al[mi], abase + ABUF_SZ + arow * 80 + ks * 32 + lcA);
            }
#pragma unroll
            for (int np = 0; np < 2; np++) {
                uint32_t krow = (uint32_t)(ks * 16 + lkB);
                uint32_t nb   = (uint32_t)(wn * 32 + np * 16 + lnB);
                uint32_t chunk = nb >> 3;
                uint32_t swz = (chunk ^ (krow & 7)) << 4;
                uint32_t bh[4], bl[4];
                ldsm_x4_t(bh, bbase + krow * 256 + swz);
                ldsm_x4_t(bl, bbase + 8192 + krow * 256 + swz);
#pragma unroll
                for (int mi = 0; mi < 4; mi++) {
                    mma_bf16(acc[mi][np*2+0], ah[mi], bh + 0);
                    mma_bf16(acc[mi][np*2+1], ah[mi], bh + 2);
                    mma_bf16(acc[mi][np*2+0], ah[mi], bl + 0);
                    mma_bf16(acc[mi][np*2+1], ah[mi], bl + 2);
                    mma_bf16(acc[mi][np*2+0], al[mi], bh + 0);
                    mma_bf16(acc[mi][np*2+1], al[mi], bh + 2);
                }
            }
        }
    }

    int er = lane >> 2, ec = (lane & 3) * 2;
#pragma unroll
    for (int mi = 0; mi < 4; mi++) {
#pragma unroll
        for (int ni = 0; ni < 4; ni++) {
            int row = co0 + wm * 64 + mi * 16 + er;
            int col = n0 + wn * 32 + ni * 8 + ec;
            size_t g0 = (size_t)(b * CC + row) * HWP + col;
            size_t g1 = g0 + 8 * HWP;
            float2 s0 = *(const float2*)(skip + g0);
            float2 s1 = *(const float2*)(skip + g1);
            float2 o0 = make_float2(acc[mi][ni][0] + s0.x, acc[mi][ni][1] + s0.y);
            float2 o1 = make_float2(acc[mi][ni][2] + s1.x, acc[mi][ni][3] + s1.y);
            *(float2*)(out + g0) = o0;
            *(float2*)(out + g1) = o1;
        }
    }
}

// ===========================================================================
extern "C" void kernel_launch(void* const* d_in, const int* in_sizes, int n_in,
                              void* d_out, int out_size) {
    const float* skip   = (const float*)d_in[0];
    const float* dec    = (const float*)d_in[1];
    const float* w_fea  = (const float*)d_in[2];
    const float* sigma1 = (const float*)d_in[3];
    const float* sigma2 = (const float*)d_in[4];
    const float* mixerw = (const float*)d_in[5];
    float* out = (float*)d_out;

    k_params<<<1, CC>>>(sigma1, sigma2);
    k_wsplit<<<CC*CC/256, 256>>>(mixerw);

    cudaFuncSetAttribute(k_plane, cudaFuncAttributeMaxDynamicSharedMemorySize,
                         PLANE_SMEM);
    k_plane<<<BB*CC, PT, PLANE_SMEM>>>((const float4*)dec, (const float4*)skip,
                                       w_fea);

    cudaFuncSetAttribute(k_gemm_mma, cudaFuncAttributeMaxDynamicSharedMemorySize,
                         GEMM_SMEM);
    dim3 grid(HWP / 128, CC / 128, BB);
    k_gemm_mma<<<grid, 256, GEMM_SMEM>>>(skip, out);
}

// round 6
// speedup vs baseline: 2.5283x; 1.0453x over previous
#include <cuda_runtime.h>
#include <cuda_bf16.h>
#include <math.h>
#include <stdint.h>

// ---- problem constants ----
#define BB 16
#define CC 256
#define HH 96
#define WW 96
#define HWP (HH*WW)                 // 9216
#define NELEM (BB*CC*HWP)           // 37748736
#define S0 24
#define S1 48
#define S2 72

// ---- scratch (device globals: allocation-free rule) ----
__device__ __nv_bfloat16 g_zh[NELEM];
__device__ __nv_bfloat16 g_zl[NELEM];
__device__ __nv_bfloat16 g_wh[CC*CC];
__device__ __nv_bfloat16 g_wl[CC*CC];
__device__ float g_dogk[CC*3];

// ===========================================================================
// PTX helpers
// ===========================================================================
__device__ __forceinline__ uint32_t smem_u32(const void* p) {
    uint32_t a;
    asm("{ .reg .u64 t; cvta.to.shared.u64 t, %1; cvt.u32.u64 %0, t; }"
        : "=r"(a) : "l"(p));
    return a;
}
#define CP16(dst, src) asm volatile( \
    "cp.async.cg.shared.global [%0], [%1], 16;" :: "r"(dst), "l"(src) : "memory")
#define CP_COMMIT() asm volatile("cp.async.commit_group;" ::: "memory")
#define CP_WAIT1() asm volatile("cp.async.wait_group 1;" ::: "memory")
#define CP_WAIT0() asm volatile("cp.async.wait_group 0;" ::: "memory")

__device__ __forceinline__ void ldsm_x4(uint32_t* r, uint32_t addr) {
    asm volatile("ldmatrix.sync.aligned.m8n8.x4.shared.b16 {%0,%1,%2,%3}, [%4];"
                 : "=r"(r[0]), "=r"(r[1]), "=r"(r[2]), "=r"(r[3]) : "r"(addr));
}
__device__ __forceinline__ void ldsm_x4_t(uint32_t* r, uint32_t addr) {
    asm volatile("ldmatrix.sync.aligned.m8n8.x4.trans.shared.b16 {%0,%1,%2,%3}, [%4];"
                 : "=r"(r[0]), "=r"(r[1]), "=r"(r[2]), "=r"(r[3]) : "r"(addr));
}
__device__ __forceinline__ void mma_bf16(float* c, const uint32_t* a, const uint32_t* b) {
    asm volatile(
        "mma.sync.aligned.m16n8k16.row.col.f32.bf16.bf16.f32 "
        "{%0,%1,%2,%3}, {%4,%5,%6,%7}, {%8,%9}, {%0,%1,%2,%3};"
        : "+f"(c[0]), "+f"(c[1]), "+f"(c[2]), "+f"(c[3])
        : "r"(a[0]), "r"(a[1]), "r"(a[2]), "r"(a[3]), "r"(b[0]), "r"(b[1]));
}

// ===========================================================================
// K0: per-channel DoG difference-kernel coefficients
// ===========================================================================
__global__ void k_params(const float* __restrict__ s1r, const float* __restrict__ s2r) {
    int c = threadIdx.x;
    float s1 = 2.f / (1.f + expf(-s1r[c]));
    float s2 = 2.f / (1.f + expf(-s2r[c]));
    float e1 = expf(-1.f / (2.f * s1 * s1)); float q1 = expf(-1.f / (s1 * s1));
    float e2 = expf(-1.f / (2.f * s2 * s2)); float q2 = expf(-1.f / (s2 * s2));
    float n1 = 1.f + 4.f * e1 + 4.f * q1;
    float n2 = 1.f + 4.f * e2 + 4.f * q2;
    g_dogk[c*3+0] = 1.f/n1 - 1.f/n2;
    g_dogk[c*3+1] = e1/n1 - e2/n2;
    g_dogk[c*3+2] = q1/n1 - q2/n2;
}

// K0b: split mixer weight into bf16 hi/lo
__global__ void k_wsplit(const float* __restrict__ w) {
    int i = blockIdx.x * 256 + threadIdx.x;
    float v = w[i];
    __nv_bfloat16 h = __float2bfloat16(v);
    g_wh[i] = h;
    g_wl[i] = __float2bfloat16(v - __bfloat162float(h));
}

// ===========================================================================
// K1: fused per-plane elementwise chain. One CTA / (b,c) plane, 512 threads.
//   Coordinate math precomputed in tables (idx0 + weight per coord per scale).
// ===========================================================================
#define SMF_Y  0
#define SMF_D0 9216
#define SMF_D1 (9216+576)
#define SMF_D2 (9216+2880)
#define PLANE_SMEM ((9216+8064)*4)   // 69120 B dynamic
#define PT 512

__global__ void __launch_bounds__(PT) k_plane(const float4* __restrict__ dec,
                                              const float4* __restrict__ skip,
                                              const float* __restrict__ wfea) {
    extern __shared__ float sm[];
    // static tables: upsample idx0/weight per scale (indexed by 0..95),
    // downsample idx0/weight per local coord (bases 0/24/72 into 144)
    __shared__ int   s_ui[3][96];
    __shared__ float s_uw[3][96];
    __shared__ int   s_di[144];
    __shared__ float s_dw[144];

    int bc = blockIdx.x;
    int c  = bc % CC;
    int t  = threadIdx.x;

    // 0) fill tables (first 288 + 144 threads)
    if (t < 288) {
        int s = t / 96, o = t % 96;
        float scl = (s == 0) ? (S0/96.f) : (s == 1) ? (S1/96.f) : (S2/96.f);
        int S = (s == 0) ? S0 : (s == 1) ? S1 : S2;
        float f = fmaxf((o + 0.5f) * scl - 0.5f, 0.f);
        int i0 = (int)f;
        if (i0 > S - 1) i0 = S - 1;
        s_ui[s][o] = i0;
        s_uw[s][o] = f - (float)i0;
    } else if (t < 432) {
        int u = t - 288;                       // 0..143
        int s = (u < 24) ? 0 : (u < 72) ? 1 : 2;
        int o = (s == 0) ? u : (s == 1) ? u - 24 : u - 72;
        float sf = (s == 0) ? (96.f/S0) : (s == 1) ? (96.f/S1) : (96.f/S2);
        float f = fmaxf((o + 0.5f) * sf - 0.5f, 0.f);
        int i0 = (int)f;
        s_di[u] = i0;
        s_dw[u] = f - (float)i0;
    }

    // 1) y = dec + skip into smem
    const float4* dp = dec  + (size_t)bc * (HWP/4);
    const float4* sp = skip + (size_t)bc * (HWP/4);
    float4* y4 = (float4*)(sm + SMF_Y);
#pragma unroll
    for (int k = 0; k < 5; k++) {
        int i = k * PT + t;
        if (i < HWP/4) {
            float4 a = dp[i], b = sp[i];
            y4[i] = make_float4(a.x + b.x, a.y + b.y, a.z + b.z, a.w + b.w);
        }
    }
    __syncthreads();

    const float* sy = sm + SMF_Y;

    // 2) three bilinear downsamples into smem (8064 outputs) via tables
#pragma unroll
    for (int k = 0; k < 16; k++) {
        int i = k * PT + t;
        if (i >= 8064) break;
        int S, off, o, tb;
        if (i < 576)       { S = S0; off = SMF_D0; o = i;        tb = 0;  }
        else if (i < 2880) { S = S1; off = SMF_D1; o = i - 576;  tb = 24; }
        else               { S = S2; off = SMF_D2; o = i - 2880; tb = 72; }
        int oy = o / S, ox = o % S;
        int y0 = s_di[tb + oy];  float wy = s_dw[tb + oy];
        int x0 = s_di[tb + ox];  float wx = s_dw[tb + ox];
        int r0 = y0 * WW, r1 = min(y0 + 1, HH - 1) * WW;
        int x1 = min(x0 + 1, WW - 1);
        float v00 = sy[r0 + x0], v01 = sy[r0 + x1];
        float v10 = sy[r1 + x0], v11 = sy[r1 + x1];
        sm[off + o] = (v00*(1.f-wx) + v01*wx)*(1.f-wy) + (v10*(1.f-wx) + v11*wx)*wy;
    }
    __syncthreads();

    // 3) fused edges + DoG + combine -> zh/zl (2 px per thread, shared taps)
    float dC = g_dogk[c*3+0], dE = g_dogk[c*3+1], dX = g_dogk[c*3+2];
    float wf = wfea[c];
    const float* pyr[3] = { sm + SMF_D0, sm + SMF_D1, sm + SMF_D2 };
    size_t gbase = (size_t)bc * HWP;
    uint32_t* zh2 = (uint32_t*)(g_zh + gbase);
    uint32_t* zl2 = (uint32_t*)(g_zl + gbase);

#pragma unroll
    for (int k = 0; k < 9; k++) {
        int j = k * PT + t;          // pair index; i = 2j, both pixels same row
        int i = 2 * j;
        int h = i / WW, w = i % WW;  // w even, w+1 < 96 always

        // ---- DoG: 3 rows x 4 cols shared window ----
        float a[3][4];
        bool hu = h > 0, hd = h < HH - 1, wl = w > 0, wr2 = w < WW - 2;
#pragma unroll
        for (int r = 0; r < 3; r++) {
            int hr = h - 1 + r;
            bool hv = (r == 1) | (r == 0 ? hu : hd);
            const float* rowp = sy + hr * WW;
            a[r][0] = (hv && wl)  ? rowp[w-1] : 0.f;
            a[r][1] = hv          ? rowp[w]   : 0.f;
            a[r][2] = hv          ? rowp[w+1] : 0.f;
            a[r][3] = (hv && wr2) ? rowp[w+2] : 0.f;
        }
        float yc0 = a[1][1], yc1 = a[1][2];
        float dog0 = dC*yc0 + dE*(a[0][1]+a[2][1]+a[1][0]+a[1][2])
                   + dX*(a[0][0]+a[0][2]+a[2][0]+a[2][2]);
        float dog1 = dC*yc1 + dE*(a[0][2]+a[2][2]+a[1][1]+a[1][3])
                   + dX*(a[0][1]+a[0][3]+a[2][1]+a[2][3]);

        // ---- multi-scale edges via tables ----
        float e0[3], e1[3];
#pragma unroll
        for (int s = 0; s < 3; s++) {
            const int S = (s == 0) ? S0 : (s == 1) ? S1 : S2;
            int y0 = s_ui[s][h]; float wy = s_uw[s][h];
            int r0 = y0 * S, r1 = min(y0 + 1, S - 1) * S;
            const float* p = pyr[s];
            // pixel 0
            int xa = s_ui[s][w]; float wxa = s_uw[s][w];
            int xa1 = min(xa + 1, S - 1);
            float u0 = (p[r0+xa]*(1.f-wxa) + p[r0+xa1]*wxa)*(1.f-wy)
                     + (p[r1+xa]*(1.f-wxa) + p[r1+xa1]*wxa)*wy;
            // pixel 1
            int xb = s_ui[s][w+1]; float wxb = s_uw[s][w+1];
            int xb1 = min(xb + 1, S - 1);
            float u1 = (p[r0+xb]*(1.f-wxb) + p[r0+xb1]*wxb)*(1.f-wy)
                     + (p[r1+xb]*(1.f-wxb) + p[r1+xb1]*wxb)*wy;
            e0[s] = fabsf(yc0 - u0);
            e1[s] = fabsf(yc1 - u1);
        }
        float we0 = (fabsf(e0[0]-e0[1]) + fabsf(e0[0]-e0[2]) + fabsf(e0[1]-e0[2]))
                    * (1.f/3.f);
        float we1 = (fabsf(e1[0]-e1[1]) + fabsf(e1[0]-e1[2]) + fabsf(e1[1]-e1[2]))
                    * (1.f/3.f);

        float v0 = 3.f*yc0 + wf*we0 + dog0;
        float v1 = 3.f*yc1 + wf*we1 + dog1;
        __nv_bfloat16 h0 = __float2bfloat16(v0);
        __nv_bfloat16 h1 = __float2bfloat16(v1);
        __nv_bfloat16 l0 = __float2bfloat16(v0 - __bfloat162float(h0));
        __nv_bfloat16 l1 = __float2bfloat16(v1 - __bfloat162float(h1));
        zh2[j] = ((uint32_t)__bfloat16_as_ushort(h1) << 16)
               |  (uint32_t)__bfloat16_as_ushort(h0);
        zl2[j] = ((uint32_t)__bfloat16_as_ushort(l1) << 16)
               |  (uint32_t)__bfloat16_as_ushort(l0);
    }
}

// ===========================================================================
// K4: HMMA split-bf16 GEMM (R4 config: 2-stage, measured 175.5us)
// ===========================================================================
#define ABUF_SZ 10240
#define BUF_STRIDE 36864            // 2*10240 + 2*8192
#define GEMM_SMEM (2*BUF_STRIDE)    // 73728

__global__ void __launch_bounds__(256, 2) k_gemm_mma(
        const float* __restrict__ skip, float* __restrict__ out) {
    extern __shared__ char smem_raw[];
    uint32_t sb = smem_u32(smem_raw);

    int t = threadIdx.x, wid = t >> 5, lane = t & 31;
    int wm = wid & 1, wn = wid >> 1;
    int b = blockIdx.z, co0 = blockIdx.y * 128, n0 = blockIdx.x * 128;

    const __nv_bfloat16* whlo[2] = { g_wh, g_wl };
    const __nv_bfloat16* zhlo[2] = { g_zh, g_zl };

    auto load_chunk = [&](int kc, int d) {
        uint32_t base = sb + d * BUF_STRIDE;
#pragma unroll
        for (int j = 0; j < 4; j++) {            // A
            int idx = j * 256 + t;
            int hl = idx >> 9, rem = idx & 511;
            int row = rem >> 2, c = rem & 3;
            const __nv_bfloat16* src = whlo[hl] + (co0 + row) * CC + kc * 32 + c * 8;
            CP16(base + hl * ABUF_SZ + row * 80 + c * 16, src);
        }
#pragma unroll
        for (int j = 0; j < 4; j++) {            // B
            int idx = j * 256 + t;
            int hl = idx >> 9, rem = idx & 511;
            int row = rem >> 4, c = rem & 15;
            const __nv_bfloat16* src = zhlo[hl]
                + (size_t)(b * CC + kc * 32 + row) * HWP + n0 + c * 8;
            CP16(base + 2 * ABUF_SZ + hl * 8192 + row * 256
                 + (uint32_t)((c ^ (row & 7)) << 4), src);
        }
    };

    float acc[4][4][4];
#pragma unroll
    for (int i = 0; i < 4; i++)
#pragma unroll
        for (int j = 0; j < 4; j++)
#pragma unroll
            for (int k = 0; k < 4; k++) acc[i][j][k] = 0.f;

    int lt = lane >> 3;
    int lrA = (lane & 7) + ((lt & 1) << 3);
    int lcA = (lt >> 1) << 4;
    int lkB = (lane & 7) + ((lt & 1) << 3);
    int lnB = (lt >> 1) << 3;

    load_chunk(0, 0);
    CP_COMMIT();

    for (int kc = 0; kc < 8; kc++) {
        int d = kc & 1;
        if (kc + 1 < 8) { load_chunk(kc + 1, d ^ 1); CP_COMMIT(); CP_WAIT1(); }
        else           { CP_WAIT0(); }
        __syncthreads();

        uint32_t abase = sb + d * BUF_STRIDE;
        uint32_t bbase = abase + 2 * ABUF_SZ;

#pragma unroll
        for (int ks = 0; ks < 2; ks++) {
            uint32_t ah[4][4], al[4][4];
#pragma unroll
            for (int mi = 0; mi < 4; mi++) {
                uint32_t arow = (uint32_t)(wm * 64 + mi * 16 + lrA);
                ldsm_x4(ah[mi], abase + arow * 80 + ks * 32 + lcA);
                ldsm_x4(al[mi], abase + ABUF_SZ + arow * 80 + ks * 32 + lcA);
            }
#pragma unroll
            for (int np = 0; np < 2; np++) {
                uint32_t krow = (uint32_t)(ks * 16 + lkB);
                uint32_t nb   = (uint32_t)(wn * 32 + np * 16 + lnB);
                uint32_t chunk = nb >> 3;
                uint32_t swz = (chunk ^ (krow & 7)) << 4;
                uint32_t bh[4], bl[4];
                ldsm_x4_t(bh, bbase + krow * 256 + swz);
                ldsm_x4_t(bl, bbase + 8192 + krow * 256 + swz);
#pragma unroll
                for (int mi = 0; mi < 4; mi++) {
                    mma_bf16(acc[mi][np*2+0], ah[mi], bh + 0);
                    mma_bf16(acc[mi][np*2+1], ah[mi], bh + 2);
                    mma_bf16(acc[mi][np*2+0], ah[mi], bl + 0);
                    mma_bf16(acc[mi][np*2+1], ah[mi], bl + 2);
                    mma_bf16(acc[mi][np*2+0], al[mi], bh + 0);
                    mma_bf16(acc[mi][np*2+1], al[mi], bh + 2);
                }
            }
        }
        __syncthreads();
    }

    int er = lane >> 2, ec = (lane & 3) * 2;
#pragma unroll
    for (int mi = 0; mi < 4; mi++) {
#pragma unroll
        for (int ni = 0; ni < 4; ni++) {
            int row = co0 + wm * 64 + mi * 16 + er;
            int col = n0 + wn * 32 + ni * 8 + ec;
            size_t g0 = (size_t)(b * CC + row) * HWP + col;
            size_t g1 = g0 + 8 * HWP;
            float2 s0 = *(const float2*)(skip + g0);
            float2 s1 = *(const float2*)(skip + g1);
            float2 o0 = make_float2(acc[mi][ni][0] + s0.x, acc[mi][ni][1] + s0.y);
            float2 o1 = make_float2(acc[mi][ni][2] + s1.x, acc[mi][ni][3] + s1.y);
            *(float2*)(out + g0) = o0;
            *(float2*)(out + g1) = o1;
        }
    }
}

// ===========================================================================
extern "C" void kernel_launch(void* const* d_in, const int* in_sizes, int n_in,
                              void* d_out, int out_size) {
    const float* skip   = (const float*)d_in[0];
    const float* dec    = (const float*)d_in[1];
    const float* w_fea  = (const float*)d_in[2];
    const float* sigma1 = (const float*)d_in[3];
    const float* sigma2 = (const float*)d_in[4];
    const float* mixerw = (const float*)d_in[5];
    float* out = (float*)d_out;

    k_params<<<1, CC>>>(sigma1, sigma2);
    k_wsplit<<<CC*CC/256, 256>>>(mixerw);

    cudaFuncSetAttribute(k_plane, cudaFuncAttributeMaxDynamicSharedMemorySize,
                         PLANE_SMEM);
    k_plane<<<BB*CC, PT, PLANE_SMEM>>>((const float4*)dec, (const float4*)skip,
                                       w_fea);

    cudaFuncSetAttribute(k_gemm_mma, cudaFuncAttributeMaxDynamicSharedMemorySize,
                         GEMM_SMEM);
    dim3 grid(HWP / 128, CC / 128, BB);
    k_gemm_mma<<<grid, 256, GEMM_SMEM>>>(skip, out);
}